// round 2
// baseline (speedup 1.0000x reference)
#include <cuda_runtime.h>
#include <cstdint>

// Problem constants (from reference_code)
#define NN 50000
#define DD 128
#define EE 625000

// Scratch buffers (allocation-free rule: __device__ globals)
__device__ float g_agg[(size_t)NN * DD];
__device__ float g_h[(size_t)NN * DD];

// ---------------------------------------------------------------------------
// Zero kernel: clear agg buffer (float4 stores)
// ---------------------------------------------------------------------------
__global__ void zero_kernel(float4* __restrict__ p, int n4) {
    int i = blockIdx.x * blockDim.x + threadIdx.x;
    if (i < n4) p[i] = make_float4(0.f, 0.f, 0.f, 0.f);
}

// ---------------------------------------------------------------------------
// Scatter-aggregate: one warp per edge.
//   agg[dst] += feat[src]   (128 floats = 32 lanes x float4)
// edge_index is int32 (JAX x64 disabled -> int64 request silently becomes
// int32). Uses red.global.add.v4.f32 to quarter the atomic op count.
// ---------------------------------------------------------------------------
__global__ void scatter_kernel(const float* __restrict__ feat,
                               const int* __restrict__ ei,
                               float* __restrict__ agg) {
    int gw = (blockIdx.x * blockDim.x + threadIdx.x) >> 5;  // global warp = edge
    int lane = threadIdx.x & 31;
    if (gw >= EE) return;
    int s = __ldg(&ei[gw]);         // src
    int d = __ldg(&ei[EE + gw]);    // dst
    float4 v = ((const float4*)(feat + (size_t)s * DD))[lane];
    float* dp = agg + (size_t)d * DD + lane * 4;
    asm volatile("red.global.add.v4.f32 [%0], {%1, %2, %3, %4};"
                 :: "l"(dp), "f"(v.x), "f"(v.y), "f"(v.z), "f"(v.w)
                 : "memory");
}

// ---------------------------------------------------------------------------
// Fused dual GEMM: out[r][c] = act( sum_k A[r][k]*Wrel[k][c]
//                                 + sum_k X[r][k]*Wroot[k][c] + bias[c] )
// Block: 256 threads, 64 rows x 128 cols tile. Both weight matrices fully in
// smem (64KB each). Input tiles padded to stride 132 (bank-conflict-free).
// Thread micro-tile: 4 rows x 8 cols.
// Dynamic smem: 2*128*128 + 2*64*132 floats = 198656 bytes.
// ---------------------------------------------------------------------------
#define AS_STRIDE 132
#define GEMM_SMEM ((2 * 128 * 128 + 2 * 64 * AS_STRIDE) * sizeof(float))

__global__ __launch_bounds__(256, 1)
void gemm_kernel(const float* __restrict__ A,      // aggregated [N, 128]
                 const float* __restrict__ X,      // root input [N, 128]
                 const float* __restrict__ Wrel,   // [128, 128]
                 const float* __restrict__ Wroot,  // [128, 128]
                 const float* __restrict__ bias,   // [128]
                 float* __restrict__ out,          // [N, 128]
                 int relu) {
    extern __shared__ float sm[];
    float* Wr = sm;                       // 128*128
    float* Wo = Wr + 128 * 128;           // 128*128
    float* As = Wo + 128 * 128;           // 64*132
    float* Xs = As + 64 * AS_STRIDE;      // 64*132

    int tid = threadIdx.x;
    int row0 = blockIdx.x * 64;

    // Stage weights (4096 float4 each; 16 per thread)
    for (int i = tid; i < 128 * 128 / 4; i += 256) {
        ((float4*)Wr)[i] = ((const float4*)Wrel)[i];
        ((float4*)Wo)[i] = ((const float4*)Wroot)[i];
    }
    // Stage input tiles: 64 rows x 32 float4 each
    int lr = tid >> 5;   // 0..7
    int lc = tid & 31;   // 0..31
    for (int r = lr; r < 64; r += 8) {
        int grow = row0 + r;
        float4 av, xv;
        if (grow < NN) {
            av = ((const float4*)(A + (size_t)grow * DD))[lc];
            xv = ((const float4*)(X + (size_t)grow * DD))[lc];
        } else {
            av = make_float4(0.f, 0.f, 0.f, 0.f);
            xv = av;
        }
        ((float4*)(As + r * AS_STRIDE))[lc] = av;
        ((float4*)(Xs + r * AS_STRIDE))[lc] = xv;
    }
    __syncthreads();

    int ty = tid >> 4;   // 0..15 -> 4 rows each
    int tx = tid & 15;   // 0..15 -> 8 cols each (stride 16)

    float acc[4][8];
#pragma unroll
    for (int i = 0; i < 4; i++)
#pragma unroll
        for (int j = 0; j < 8; j++) acc[i][j] = 0.f;

#pragma unroll 4
    for (int k = 0; k < 128; k++) {
        float a[4], xr[4], wr[8], wo[8];
#pragma unroll
        for (int i = 0; i < 4; i++) {
            a[i]  = As[(ty * 4 + i) * AS_STRIDE + k];
            xr[i] = Xs[(ty * 4 + i) * AS_STRIDE + k];
        }
#pragma unroll
        for (int j = 0; j < 8; j++) {
            wr[j] = Wr[k * 128 + tx + j * 16];
            wo[j] = Wo[k * 128 + tx + j * 16];
        }
#pragma unroll
        for (int i = 0; i < 4; i++)
#pragma unroll
            for (int j = 0; j < 8; j++)
                acc[i][j] += a[i] * wr[j] + xr[i] * wo[j];
    }

    // Writeback with bias (+ optional relu)
#pragma unroll
    for (int i = 0; i < 4; i++) {
        int grow = row0 + ty * 4 + i;
        if (grow < NN) {
#pragma unroll
            for (int j = 0; j < 8; j++) {
                int c = tx + j * 16;
                float v = acc[i][j] + __ldg(&bias[c]);
                if (relu) v = fmaxf(v, 0.f);
                out[(size_t)grow * DD + c] = v;
            }
        }
    }
}

// ---------------------------------------------------------------------------
// Launch
// ---------------------------------------------------------------------------
extern "C" void kernel_launch(void* const* d_in, const int* in_sizes, int n_in,
                              void* d_out, int out_size) {
    const float* x       = (const float*)d_in[0];
    const int*   ei      = (const int*)d_in[1];   // int32! (JAX x64 disabled)
    const float* W1_rel  = (const float*)d_in[2];
    const float* b1_rel  = (const float*)d_in[3];
    const float* W1_root = (const float*)d_in[4];
    const float* W2_rel  = (const float*)d_in[5];
    const float* b2_rel  = (const float*)d_in[6];
    const float* W2_root = (const float*)d_in[7];
    float*       out     = (float*)d_out;

    float* agg = nullptr;
    float* h   = nullptr;
    cudaGetSymbolAddress((void**)&agg, g_agg);
    cudaGetSymbolAddress((void**)&h, g_h);

    // Allow >48KB dynamic smem for the GEMM (idempotent; cheap)
    cudaFuncSetAttribute(gemm_kernel,
                         cudaFuncAttributeMaxDynamicSharedMemorySize,
                         (int)GEMM_SMEM);

    const int n4 = NN * DD / 4;
    const int zgrid = (n4 + 255) / 256;
    const int sgrid = (EE * 32 + 255) / 256;   // one warp per edge
    const int ggrid = (NN + 63) / 64;

    // Layer 1
    zero_kernel<<<zgrid, 256>>>((float4*)agg, n4);
    scatter_kernel<<<sgrid, 256>>>(x, ei, agg);
    gemm_kernel<<<ggrid, 256, GEMM_SMEM>>>(agg, x, W1_rel, W1_root, b1_rel, h, 1);

    // Layer 2
    zero_kernel<<<zgrid, 256>>>((float4*)agg, n4);
    scatter_kernel<<<sgrid, 256>>>(h, ei, agg);
    gemm_kernel<<<ggrid, 256, GEMM_SMEM>>>(agg, h, W2_rel, W2_root, b2_rel, out, 0);
}

// round 3
// speedup vs baseline: 1.3310x; 1.3310x over previous
#include <cuda_runtime.h>
#include <cstdint>

// Problem constants
#define NN 50000
#define DD 128
#define EE 625000

typedef unsigned long long u64;

// Scratch (allocation-free rule: __device__ globals)
__device__ float g_agg[(size_t)NN * DD];
__device__ float g_h[(size_t)NN * DD];

// ---------------------------------------------------------------------------
// Zero kernel
// ---------------------------------------------------------------------------
__global__ void zero_kernel(float4* __restrict__ p, int n4) {
    int i = blockIdx.x * blockDim.x + threadIdx.x;
    if (i < n4) p[i] = make_float4(0.f, 0.f, 0.f, 0.f);
}

// ---------------------------------------------------------------------------
// Scatter-aggregate: one warp per 4 edges (batched loads -> batched REDs).
//   agg[dst] += feat[src]  (128 floats = 32 lanes x float4 per edge)
// ---------------------------------------------------------------------------
#define EPW 4  // edges per warp
__global__ void scatter_kernel(const float* __restrict__ feat,
                               const int* __restrict__ ei,
                               float* __restrict__ agg) {
    int gw = (blockIdx.x * blockDim.x + threadIdx.x) >> 5;
    int lane = threadIdx.x & 31;
    int e0 = gw * EPW;
    if (e0 >= EE) return;

    float4 v[EPW];
    int d[EPW];
    int cnt = min(EPW, EE - e0);
#pragma unroll
    for (int t = 0; t < EPW; t++) {
        if (t < cnt) {
            int e = e0 + t;
            int s = __ldg(&ei[e]);
            d[t] = __ldg(&ei[EE + e]);
            v[t] = ((const float4*)(feat + (size_t)s * DD))[lane];
        }
    }
#pragma unroll
    for (int t = 0; t < EPW; t++) {
        if (t < cnt) {
            float* dp = agg + (size_t)d[t] * DD + lane * 4;
            asm volatile("red.global.add.v4.f32 [%0], {%1, %2, %3, %4};"
                         :: "l"(dp), "f"(v[t].x), "f"(v[t].y), "f"(v[t].z), "f"(v[t].w)
                         : "memory");
        }
    }
}

// ---------------------------------------------------------------------------
// Fused dual GEMM with packed f32x2 FMA (FFMA2):
//   out[r][c] = act( sum_k A[r][k]*Wrel[k][c] + sum_k X[r][k]*Wroot[k][c] + b[c] )
// Block: 256 threads, tile 128 rows x 128 cols. Thread: 8 rows x 4 col-pairs.
// Weights fully resident in smem; A/X staged in two 64-k chunks (smem budget).
// Accumulators are f32x2 (two adjacent columns per 64-bit register).
// Smem: 2*128*128 (W) + 2*128*68 (A/X chunk) floats = 200704 bytes.
// ---------------------------------------------------------------------------
#define KT 64
#define AST 68
#define GEMM_SMEM ((2 * 128 * 128 + 2 * 128 * AST) * sizeof(float))

__device__ __forceinline__ u64 pack2(float a) {
    u64 r;
    asm("mov.b64 %0, {%1, %1};" : "=l"(r) : "f"(a));
    return r;
}
__device__ __forceinline__ u64 ffma2(u64 a, u64 b, u64 c) {
    u64 d;
    asm("fma.rn.f32x2 %0, %1, %2, %3;" : "=l"(d) : "l"(a), "l"(b), "l"(c));
    return d;
}

__global__ __launch_bounds__(256, 1)
void gemm_kernel(const float* __restrict__ A,
                 const float* __restrict__ X,
                 const float* __restrict__ Wrel,
                 const float* __restrict__ Wroot,
                 const float* __restrict__ bias,
                 float* __restrict__ out,
                 int relu) {
    extern __shared__ float sm[];
    float* Wr = sm;                   // 128*128
    float* Wo = Wr + 128 * 128;       // 128*128
    float* As = Wo + 128 * 128;       // 128*AST (64-k chunk)
    float* Xs = As + 128 * AST;       // 128*AST

    int tid = threadIdx.x;
    int row0 = blockIdx.x * 128;
    int tx = tid & 15;    // 16 col groups: cols = tx*2 + j*32 (pairs)
    int ty = tid >> 4;    // 16 row groups: rows = ty*8 + i

    // Stage both weight matrices (4096 float4 each)
    for (int i = tid; i < 128 * 128 / 4; i += 256) {
        ((float4*)Wr)[i] = ((const float4*)Wrel)[i];
        ((float4*)Wo)[i] = ((const float4*)Wroot)[i];
    }

    u64 acc[8][4];
#pragma unroll
    for (int i = 0; i < 8; i++)
#pragma unroll
        for (int j = 0; j < 4; j++) acc[i][j] = 0ull;

    for (int stage = 0; stage < 2; stage++) {
        int kb = stage * KT;
        __syncthreads();
        // Stage A/X chunk: 128 rows x 16 float4
        for (int i = tid; i < 128 * 16; i += 256) {
            int r = i >> 4, c = i & 15;
            int grow = row0 + r;
            float4 av, xv;
            if (grow < NN) {
                av = ((const float4*)(A + (size_t)grow * DD + kb))[c];
                xv = ((const float4*)(X + (size_t)grow * DD + kb))[c];
            } else {
                av = make_float4(0.f, 0.f, 0.f, 0.f);
                xv = av;
            }
            ((float4*)(As + r * AST))[c] = av;
            ((float4*)(Xs + r * AST))[c] = xv;
        }
        __syncthreads();

#pragma unroll 2
        for (int kk = 0; kk < KT; kk++) {
            const float* wrk = Wr + (kb + kk) * 128;
            const float* wok = Wo + (kb + kk) * 128;
            u64 wr2[4], wo2[4];
#pragma unroll
            for (int j = 0; j < 4; j++) {
                wr2[j] = *(const u64*)(wrk + tx * 2 + j * 32);
                wo2[j] = *(const u64*)(wok + tx * 2 + j * 32);
            }
            u64 a2[8], x2[8];
#pragma unroll
            for (int i = 0; i < 8; i++) {
                a2[i] = pack2(As[(ty * 8 + i) * AST + kk]);
                x2[i] = pack2(Xs[(ty * 8 + i) * AST + kk]);
            }
#pragma unroll
            for (int i = 0; i < 8; i++)
#pragma unroll
                for (int j = 0; j < 4; j++) {
                    acc[i][j] = ffma2(a2[i], wr2[j], acc[i][j]);
                    acc[i][j] = ffma2(x2[i], wo2[j], acc[i][j]);
                }
        }
    }

    // Writeback: unpack pairs, add bias, optional relu
    float b0[4], b1[4];
#pragma unroll
    for (int j = 0; j < 4; j++) {
        int c = tx * 2 + j * 32;
        b0[j] = __ldg(&bias[c]);
        b1[j] = __ldg(&bias[c + 1]);
    }
#pragma unroll
    for (int i = 0; i < 8; i++) {
        int grow = row0 + ty * 8 + i;
        if (grow < NN) {
#pragma unroll
            for (int j = 0; j < 4; j++) {
                int c = tx * 2 + j * 32;
                float lo, hi;
                asm("mov.b64 {%0, %1}, %2;" : "=f"(lo), "=f"(hi) : "l"(acc[i][j]));
                lo += b0[j];
                hi += b1[j];
                if (relu) { lo = fmaxf(lo, 0.f); hi = fmaxf(hi, 0.f); }
                *(float2*)(out + (size_t)grow * DD + c) = make_float2(lo, hi);
            }
        }
    }
}

// ---------------------------------------------------------------------------
// Launch
// ---------------------------------------------------------------------------
extern "C" void kernel_launch(void* const* d_in, const int* in_sizes, int n_in,
                              void* d_out, int out_size) {
    const float* x       = (const float*)d_in[0];
    const int*   ei      = (const int*)d_in[1];   // int32 (JAX x64 disabled)
    const float* W1_rel  = (const float*)d_in[2];
    const float* b1_rel  = (const float*)d_in[3];
    const float* W1_root = (const float*)d_in[4];
    const float* W2_rel  = (const float*)d_in[5];
    const float* b2_rel  = (const float*)d_in[6];
    const float* W2_root = (const float*)d_in[7];
    float*       out     = (float*)d_out;

    float* agg = nullptr;
    float* h   = nullptr;
    cudaGetSymbolAddress((void**)&agg, g_agg);
    cudaGetSymbolAddress((void**)&h, g_h);

    cudaFuncSetAttribute(gemm_kernel,
                         cudaFuncAttributeMaxDynamicSharedMemorySize,
                         (int)GEMM_SMEM);

    const int n4 = NN * DD / 4;
    const int zgrid = (n4 + 255) / 256;
    const int nwarp = (EE + EPW - 1) / EPW;
    const int sgrid = (nwarp * 32 + 255) / 256;
    const int ggrid = (NN + 127) / 128;

    // Layer 1
    zero_kernel<<<zgrid, 256>>>((float4*)agg, n4);
    scatter_kernel<<<sgrid, 256>>>(x, ei, agg);
    gemm_kernel<<<ggrid, 256, GEMM_SMEM>>>(agg, x, W1_rel, W1_root, b1_rel, h, 1);

    // Layer 2
    zero_kernel<<<zgrid, 256>>>((float4*)agg, n4);
    scatter_kernel<<<sgrid, 256>>>(h, ei, agg);
    gemm_kernel<<<ggrid, 256, GEMM_SMEM>>>(agg, h, W2_rel, W2_root, b2_rel, out, 0);
}